// round 1
// baseline (speedup 1.0000x reference)
#include <cuda_runtime.h>
#include <cstdint>
#include <math.h>

#define N_TOK 1024
#define HID   2048
#define NEXP  8
#define IMOE  1408
#define ISH   5632

// ---------------- scratch (device globals; no allocation allowed) ----------------
__device__ float g_gu_s [(size_t)N_TOK * (2 * ISH)];        // shared gate_up out
__device__ float g_act_s[(size_t)N_TOK * ISH];              // shared activated
__device__ float g_gu_e [(size_t)NEXP * N_TOK * (2 * IMOE)];// expert gate_up out (compact)
__device__ float g_act_e[(size_t)NEXP * N_TOK * IMOE];      // expert activated (compact, route-weighted)
__device__ float g_part [(size_t)N_TOK * 2 * HID];          // per-(token,slot) expert contribution
__device__ float g_sg  [N_TOK];                             // sigmoid shared gate
__device__ float g_wt  [NEXP * N_TOK];                      // routing weight per list entry
__device__ int   g_cnt [NEXP];
__device__ int   g_tok [NEXP * N_TOK];
__device__ int   g_slot[NEXP * N_TOK];

// ---------------- small helpers ----------------
__device__ __forceinline__ float siluf(float v) { return v / (1.f + expf(-v)); }

__device__ __forceinline__ unsigned f2tf(float f) {
    unsigned r; asm("cvt.rna.tf32.f32 %0, %1;" : "=r"(r) : "f"(f)); return r;
}
__device__ __forceinline__ float4 tf4(float4 v) {
    float4 o;
    o.x = __uint_as_float(f2tf(v.x));
    o.y = __uint_as_float(f2tf(v.y));
    o.z = __uint_as_float(f2tf(v.z));
    o.w = __uint_as_float(f2tf(v.w));
    return o;
}
__device__ __forceinline__ void mma_tf32(float* c, const unsigned* a, const unsigned* b) {
    asm volatile(
        "mma.sync.aligned.m16n8k8.row.col.f32.tf32.tf32.f32 "
        "{%0,%1,%2,%3}, {%4,%5,%6,%7}, {%8,%9}, {%0,%1,%2,%3};\n"
        : "+f"(c[0]), "+f"(c[1]), "+f"(c[2]), "+f"(c[3])
        : "r"(a[0]), "r"(a[1]), "r"(a[2]), "r"(a[3]), "r"(b[0]), "r"(b[1]));
}

// ---------------- init: zero per-expert counters (must run every replay) ----------------
__global__ void init_kernel() {
    if (threadIdx.x < NEXP) g_cnt[threadIdx.x] = 0;
}

// ---------------- router: logits, softmax, top-2, sigmoid shared gate ----------------
__global__ void router_kernel(const float* __restrict__ x,
                              const float* __restrict__ gate_w,
                              const float* __restrict__ sgate_w) {
    int n = blockIdx.x;
    int w = threadIdx.x >> 5, lane = threadIdx.x & 31;
    const float* xr = x + (size_t)n * HID;
    __shared__ float s_log[NEXP];
    __shared__ float s_sg;

    float acc = 0.f, accs = 0.f;
    for (int h = lane; h < HID; h += 32) {
        float xv = xr[h];
        acc += xv * gate_w[h * NEXP + w];
        if (w == 0) accs += xv * sgate_w[h];
    }
    #pragma unroll
    for (int o = 16; o > 0; o >>= 1) {
        acc  += __shfl_down_sync(0xffffffffu, acc, o);
        accs += __shfl_down_sync(0xffffffffu, accs, o);
    }
    if (lane == 0) { s_log[w] = acc; if (w == 0) s_sg = accs; }
    __syncthreads();

    if (threadIdx.x == 0) {
        float mx = s_log[0];
        #pragma unroll
        for (int e = 1; e < NEXP; e++) mx = fmaxf(mx, s_log[e]);
        float p[NEXP], den = 0.f;
        #pragma unroll
        for (int e = 0; e < NEXP; e++) { p[e] = expf(s_log[e] - mx); den += p[e]; }
        float inv = 1.f / den;
        #pragma unroll
        for (int e = 0; e < NEXP; e++) p[e] *= inv;
        // top-2, ties -> lowest index (matches jax.lax.top_k)
        int e0 = 0;
        #pragma unroll
        for (int e = 1; e < NEXP; e++) if (p[e] > p[e0]) e0 = e;
        int e1 = (e0 == 0) ? 1 : 0;
        #pragma unroll
        for (int e = 0; e < NEXP; e++) if (e != e0 && p[e] > p[e1]) e1 = e;
        int es[2] = {e0, e1};
        #pragma unroll
        for (int k = 0; k < 2; k++) {
            int e = es[k];
            int pos = atomicAdd(&g_cnt[e], 1);
            g_tok [e * N_TOK + pos] = n;
            g_slot[e * N_TOK + pos] = k;
            g_wt  [e * N_TOK + pos] = p[e];
        }
        g_sg[n] = 1.f / (1.f + expf(-s_sg));
    }
}

// ---------------- tf32 GEMM, 128x128x16 tile, 256 threads ----------------
// MODE 0: C(g_gu_s)      = x      @ shared_w_gate_up           [1024,2048]x[2048,11264]
// MODE 1: out            = act_s  @ shared_w_down  * sg[row]   [1024,5632]x[5632,2048]
// MODE 2: g_gu_e[e]      = gather(x) @ w_gate_up[e]            [cnt,2048]x[2048,2816]
// MODE 3: g_part[tok,sl] = g_act_e[e] @ w_down[e]              [cnt,1408]x[1408,2048]
#define BM 128
#define BN 128
#define BK 16
#define GT 256

template<int MODE>
__global__ void __launch_bounds__(GT)
gemm_tf32(const float* __restrict__ Ag, const float* __restrict__ Bg,
          float* __restrict__ Cg, int M, int K, int N) {
    __shared__ float As[2][BM][BK + 4];   // conflict-free for frag pattern
    __shared__ float Bs[2][BK][BN + 8];

    const int tid  = threadIdx.x;
    const int lane = tid & 31, warp = tid >> 5;
    const int wm = warp & 1, wn = warp >> 1;      // 2x4 warp grid -> 64x32 warp tile
    const int g = lane >> 2, tg = lane & 3;

    const int m0 = blockIdx.y * BM;
    const int n0 = blockIdx.x * BN;
    const int e  = blockIdx.z;

    int Mrows = M;
    const float* B = Bg;
    if (MODE == 2 || MODE == 3) {
        Mrows = g_cnt[e];
        B = Bg + (size_t)e * (size_t)K * (size_t)N;
        if (m0 >= Mrows) return;
    }

    const float* Abase;
    if (MODE == 1)      Abase = g_act_s;
    else if (MODE == 3) Abase = g_act_e + (size_t)e * N_TOK * (size_t)K;
    else                Abase = Ag;

    // A loader: thread covers (row r0, cols kq*4..) and (row r1, same cols)
    const int lr0 = tid >> 2;            // 0..63
    const int lr1 = lr0 + 64;            // 64..127
    const int kq  = (tid & 3) * 4;
    const float *aP0, *aP1;
    {
        int rr0 = m0 + lr0, rr1 = m0 + lr1;
        if (MODE == 2) {
            int i0 = (rr0 < Mrows) ? g_tok[e * N_TOK + rr0] : 0;
            int i1 = (rr1 < Mrows) ? g_tok[e * N_TOK + rr1] : 0;
            aP0 = Ag + (size_t)i0 * (size_t)K;
            aP1 = Ag + (size_t)i1 * (size_t)K;
        } else {
            aP0 = Abase + (size_t)rr0 * (size_t)K;
            aP1 = Abase + (size_t)rr1 * (size_t)K;
        }
    }
    // B loader
    const int bk0 = tid >> 5, bk1 = bk0 + 8;
    const int bn  = (tid & 31) * 4;

    float acc[4][4][4];
    #pragma unroll
    for (int i = 0; i < 4; i++)
        #pragma unroll
        for (int j = 0; j < 4; j++)
            #pragma unroll
            for (int q = 0; q < 4; q++) acc[i][j][q] = 0.f;

    const int ktiles = K / BK;
    float4 x0, x1, y0, y1;

    // prologue: tile 0 -> buf 0
    x0 = *(const float4*)(aP0 + kq);
    x1 = *(const float4*)(aP1 + kq);
    y0 = *(const float4*)(B + (size_t)bk0 * N + n0 + bn);
    y1 = *(const float4*)(B + (size_t)bk1 * N + n0 + bn);
    *(float4*)&As[0][lr0][kq] = tf4(x0);
    *(float4*)&As[0][lr1][kq] = tf4(x1);
    *(float4*)&Bs[0][bk0][bn] = tf4(y0);
    *(float4*)&Bs[0][bk1][bn] = tf4(y1);
    __syncthreads();

    for (int kt = 0; kt < ktiles; kt++) {
        const int buf = kt & 1;
        if (kt + 1 < ktiles) {
            const int k0 = (kt + 1) * BK;
            x0 = *(const float4*)(aP0 + k0 + kq);
            x1 = *(const float4*)(aP1 + k0 + kq);
            y0 = *(const float4*)(B + (size_t)(k0 + bk0) * N + n0 + bn);
            y1 = *(const float4*)(B + (size_t)(k0 + bk1) * N + n0 + bn);
        }
        // compute on buf
        #pragma unroll
        for (int ks = 0; ks < 2; ks++) {
            const int kk = ks * 8;
            unsigned af[4][4], bf[4][2];
            #pragma unroll
            for (int i = 0; i < 4; i++) {
                int r = wm * 64 + i * 16;
                af[i][0] = __float_as_uint(As[buf][r + g    ][kk + tg    ]);
                af[i][1] = __float_as_uint(As[buf][r + g + 8][kk + tg    ]);
                af[i][2] = __float_as_uint(As[buf][r + g    ][kk + tg + 4]);
                af[i][3] = __float_as_uint(As[buf][r + g + 8][kk + tg + 4]);
            }
            #pragma unroll
            for (int j = 0; j < 4; j++) {
                int c = wn * 32 + j * 8 + g;
                bf[j][0] = __float_as_uint(Bs[buf][kk + tg    ][c]);
                bf[j][1] = __float_as_uint(Bs[buf][kk + tg + 4][c]);
            }
            #pragma unroll
            for (int i = 0; i < 4; i++)
                #pragma unroll
                for (int j = 0; j < 4; j++)
                    mma_tf32(acc[i][j], af[i], bf[j]);
        }
        if (kt + 1 < ktiles) {
            *(float4*)&As[buf ^ 1][lr0][kq] = tf4(x0);
            *(float4*)&As[buf ^ 1][lr1][kq] = tf4(x1);
            *(float4*)&Bs[buf ^ 1][bk0][bn] = tf4(y0);
            *(float4*)&Bs[buf ^ 1][bk1][bn] = tf4(y1);
            __syncthreads();
        }
    }

    // epilogue
    #pragma unroll
    for (int i = 0; i < 4; i++) {
        #pragma unroll
        for (int half = 0; half < 2; half++) {
            int lr = wm * 64 + i * 16 + g + half * 8;
            int gr = m0 + lr;
            if ((MODE == 2 || MODE == 3) && gr >= Mrows) continue;
            float* crow;
            float scale = 1.f;
            if (MODE == 0)      crow = g_gu_s + (size_t)gr * N;
            else if (MODE == 1) { crow = Cg + (size_t)gr * N; scale = g_sg[gr]; }
            else if (MODE == 2) crow = g_gu_e + ((size_t)e * N_TOK + gr) * (size_t)N;
            else {
                int t_ = g_tok [e * N_TOK + gr];
                int s_ = g_slot[e * N_TOK + gr];
                crow = g_part + ((size_t)t_ * 2 + s_) * (size_t)N;
            }
            #pragma unroll
            for (int j = 0; j < 4; j++) {
                int cc = n0 + wn * 32 + j * 8 + 2 * tg;
                float2 v = make_float2(acc[i][j][half * 2 + 0] * scale,
                                       acc[i][j][half * 2 + 1] * scale);
                *(float2*)(crow + cc) = v;
            }
        }
    }
}

// ---------------- elementwise: shared silu*up ----------------
__global__ void silu_shared_kernel() {
    int idx = blockIdx.x * blockDim.x + threadIdx.x;
    const int total = N_TOK * (ISH / 4);
    if (idx >= total) return;
    int n  = idx / (ISH / 4);
    int i4 = (idx % (ISH / 4)) * 4;
    const float* row = g_gu_s + (size_t)n * (2 * ISH);
    float4 gv = *(const float4*)(row + i4);
    float4 uv = *(const float4*)(row + ISH + i4);
    float4 o = make_float4(siluf(gv.x) * uv.x, siluf(gv.y) * uv.y,
                           siluf(gv.z) * uv.z, siluf(gv.w) * uv.w);
    *(float4*)(g_act_s + (size_t)n * ISH + i4) = o;
}

// ---------------- elementwise: expert silu*up, scaled by routing weight ----------------
__global__ void silu_expert_kernel() {
    int idx = blockIdx.x * blockDim.x + threadIdx.x;
    const int per = IMOE / 4;                 // 352
    const int total = NEXP * N_TOK * per;
    if (idx >= total) return;
    int e   = idx / (N_TOK * per);
    int rem = idx % (N_TOK * per);
    int m   = rem / per;
    int i4  = (rem % per) * 4;
    if (m >= g_cnt[e]) return;
    float w = g_wt[e * N_TOK + m];
    const float* row = g_gu_e + ((size_t)e * N_TOK + m) * (2 * IMOE);
    float4 gv = *(const float4*)(row + i4);
    float4 uv = *(const float4*)(row + IMOE + i4);
    float4 o = make_float4(w * siluf(gv.x) * uv.x, w * siluf(gv.y) * uv.y,
                           w * siluf(gv.z) * uv.z, w * siluf(gv.w) * uv.w);
    *(float4*)(g_act_e + ((size_t)e * N_TOK + m) * IMOE + i4) = o;
}

// ---------------- combine: out += part[slot0] + part[slot1] ----------------
__global__ void combine_kernel(float* __restrict__ out) {
    int idx = blockIdx.x * blockDim.x + threadIdx.x;
    const int total = N_TOK * (HID / 4);
    if (idx >= total) return;
    int n  = idx / (HID / 4);
    int h4 = (idx % (HID / 4)) * 4;
    float4 o  = *(float4*)(out + (size_t)n * HID + h4);
    float4 p0 = *(const float4*)(g_part + ((size_t)n * 2 + 0) * HID + h4);
    float4 p1 = *(const float4*)(g_part + ((size_t)n * 2 + 1) * HID + h4);
    o.x += p0.x + p1.x; o.y += p0.y + p1.y;
    o.z += p0.z + p1.z; o.w += p0.w + p1.w;
    *(float4*)(out + (size_t)n * HID + h4) = o;
}

// ---------------- launch ----------------
extern "C" void kernel_launch(void* const* d_in, const int* in_sizes, int n_in,
                              void* d_out, int out_size) {
    const float* x    = (const float*)d_in[0];   // [1024, 2048]
    const float* gw   = (const float*)d_in[1];   // [2048, 8]
    const float* wgu  = (const float*)d_in[2];   // [8, 2048, 2816]
    const float* wd   = (const float*)d_in[3];   // [8, 1408, 2048]
    const float* swgu = (const float*)d_in[4];   // [2048, 11264]
    const float* swd  = (const float*)d_in[5];   // [5632, 2048]
    const float* sgw  = (const float*)d_in[6];   // [2048, 1]
    float* out = (float*)d_out;                  // [1024, 2048]

    init_kernel<<<1, 32>>>();
    router_kernel<<<N_TOK, 256>>>(x, gw, sgw);

    // shared expert chain
    gemm_tf32<0><<<dim3((2 * ISH) / BN, N_TOK / BM, 1), GT>>>(x, swgu, nullptr, N_TOK, HID, 2 * ISH);
    {
        int total = N_TOK * (ISH / 4);
        silu_shared_kernel<<<(total + 255) / 256, 256>>>();
    }
    gemm_tf32<1><<<dim3(HID / BN, N_TOK / BM, 1), GT>>>(nullptr, swd, out, N_TOK, ISH, HID);

    // routed experts (gathered)
    gemm_tf32<2><<<dim3((2 * IMOE) / BN, N_TOK / BM, NEXP), GT>>>(x, wgu, nullptr, N_TOK, HID, 2 * IMOE);
    {
        int total = NEXP * N_TOK * (IMOE / 4);
        silu_expert_kernel<<<(total + 255) / 256, 256>>>();
    }
    gemm_tf32<3><<<dim3(HID / BN, N_TOK / BM, NEXP), GT>>>(nullptr, wd, nullptr, N_TOK, IMOE, HID);

    {
        int total = N_TOK * (HID / 4);
        combine_kernel<<<(total + 255) / 256, 256>>>(out);
    }
}